// round 16
// baseline (speedup 1.0000x reference)
#include <cuda_runtime.h>
#include <cuda_bf16.h>
#include <math.h>

#define NN 50000
#define EE 800000
#define DD 128
#define MAXN 4
#define SLOT_INF 0xFFFFFFFFu
#define NBLOCKS 444            // 148 SMs x 3 resident blocks (co-resident by construction)
#define NPB 113                // ceil(50000/444) nodes per block
#define NIT 15                 // ceil(113/8) iterations per sub-lane
#define SCAT_BLOCKS ((EE / 4 + 255) / 256)
#define NBUCKET 782            // ceil(50048/64) buckets of 64 nodes
#define MAXB 2048              // bucket capacity (mean 1024, sigma ~32)

// ---------------- scratch (device globals; no allocation allowed) ----------
__device__ unsigned long long g_bedge[(size_t)NBUCKET * MAXB];  // (node<<32)|edge
__device__ int      g_bcnt[NBUCKET];       // zero-init; reset by bucket kernel
__device__ int4     g_srcn[NN];            // 4 source NODE ids per node (-1 = empty)
__device__ float    g_blankp[2][DD];
__device__ float    g_sum[2][DD];
__device__ float    g_sq[2][DD];
__device__ int      g_done[2];

// ---------------- kernels ---------------------------------------------------

// Scatter edges into dst-buckets: one spread atomicAdd + one 8B store per
// edge — pure throughput, no atomic chains. Extra block: blankp + stat-zero.
__global__ void scatter_kernel(const int4* __restrict__ dst4,
                               const float* __restrict__ W0, const float* __restrict__ b0,
                               const float* __restrict__ blank0,
                               const float* __restrict__ W1, const float* __restrict__ b1,
                               const float* __restrict__ blank1)
{
    if ((int)blockIdx.x < SCAT_BLOCKS) {
        int t = blockIdx.x * blockDim.x + threadIdx.x;
        if (t >= EE / 4) return;
        int4 d = __ldg(&dst4[t]);
        unsigned e0 = (unsigned)(t * 4);
#pragma unroll
        for (int j = 0; j < 4; j++) {
            int node = (j == 0) ? d.x : (j == 1) ? d.y : (j == 2) ? d.z : d.w;
            int bucket = node >> 6;
            int pos = atomicAdd(&g_bcnt[bucket], 1);
            if (pos < MAXB)
                g_bedge[(size_t)bucket * MAXB + pos] =
                    ((unsigned long long)(unsigned)node << 32) | (e0 + (unsigned)j);
        }
    } else {
        int t = threadIdx.x;           // 0..255
        int layer = t >> 7;            // 0 or 1
        int d = t & 127;
        const float* W  = layer ? W1 : W0;
        const float* b  = layer ? b1 : b0;
        const float* bl = layer ? blank1 : blank0;
        float s = b[d];
#pragma unroll 8
        for (int j = 0; j < DD; j++) s += W[d * DD + j] * bl[j];
        g_blankp[layer][d] = s;
        g_sum[layer][d] = 0.0f;
        g_sq[layer][d]  = 0.0f;
        if (t == 0) { g_done[0] = 0; g_done[1] = 0; }
    }
}

// Per-bucket top-4 in SHARED memory: smem atomicMin cascade (~30cyc vs 318cyc
// global), then convert slot edge-ids -> source node ids and write g_srcn.
// Also resets this bucket's counter so graph replays are deterministic.
__global__ __launch_bounds__(256) void bucket_kernel(const int* __restrict__ src)
{
    __shared__ unsigned uslot[64 * MAXN];   // 64 nodes x 4 slots
    int tid = threadIdx.x;
    int b = blockIdx.x;

    uslot[tid] = SLOT_INF;                  // 256 = 64*4 exactly
    __syncthreads();

    int cnt = g_bcnt[b];
    if (cnt > MAXB) cnt = MAXB;

    for (int i = tid; i < cnt; i += 256) {
        unsigned long long v = g_bedge[(size_t)b * MAXB + i];
        unsigned e = (unsigned)v;
        int local = (int)(v >> 32) & 63;
        unsigned* sl = &uslot[local * MAXN];
        if (e >= sl[MAXN - 1]) continue;    // smem prune (stale-high safe)
        unsigned val = e;
#pragma unroll
        for (int k = 0; k < MAXN; k++) {
            unsigned old = atomicMin(&sl[k], val);
            if (old == SLOT_INF) break;
            val = max(val, old);
        }
    }
    __syncthreads();

    if (tid < 64) {
        int node = (b << 6) + tid;
        if (node < NN) {
            unsigned s0 = uslot[tid * MAXN + 0];
            unsigned s1 = uslot[tid * MAXN + 1];
            unsigned s2 = uslot[tid * MAXN + 2];
            unsigned s3 = uslot[tid * MAXN + 3];
            int4 r;
            r.x = (s0 == SLOT_INF) ? -1 : __ldg(&src[s0]);
            r.y = (s1 == SLOT_INF) ? -1 : __ldg(&src[s1]);
            r.z = (s2 == SLOT_INF) ? -1 : __ldg(&src[s2]);
            r.w = (s3 == SLOT_INF) ? -1 : __ldg(&src[s3]);
            g_srcn[node] = r;
        }
    }
    if (tid == 0) g_bcnt[b] = 0;            // reset for next replay
}

// Fused persistent conv + batchnorm-apply, software-pipelined phase 1.
__global__ __launch_bounds__(256, 3) void fused_kernel(
    const float4* __restrict__ x4,
    const float* __restrict__ cw, const float* __restrict__ cb,
    const float* __restrict__ a_p,
    const float* __restrict__ gamma, const float* __restrict__ beta,
    float4* __restrict__ out4, int layer)
{
    extern __shared__ float4 sh[];          // [NPB][32] h rows
    __shared__ int4   s_srcn[NPB];
    __shared__ float4 ssum[256];
    __shared__ float4 ssq[256];
    __shared__ float  smu[DD];
    __shared__ float  sscale[DD];

    int dg  = threadIdx.x & 31;    // dim group: dims 4*dg .. 4*dg+3
    int sub = threadIdx.x >> 5;    // 0..7 node sub-lanes
    float c0 = __ldg(cw + 0), c1 = __ldg(cw + 1), c2 = __ldg(cw + 2), c3 = __ldg(cw + 3);
    float cbv = __ldg(cb);
    float av  = __ldg(a_p);
    float4 bp = *reinterpret_cast<const float4*>(&g_blankp[layer][dg * 4]);

    int blockStart = blockIdx.x * NPB;

    // ---- phase 0: coalesced srcn preload ----
    for (int k = threadIdx.x; k < NPB; k += 256) {
        int i = blockStart + k;
        s_srcn[k] = (i < NN) ? g_srcn[i] : make_int4(-1, -1, -1, -1);
    }
    __syncthreads();

    float4 lsum = make_float4(0.f, 0.f, 0.f, 0.f);
    float4 lsq  = make_float4(0.f, 0.f, 0.f, 0.f);

    // ---- phase 1: conv into smem, 2-stage software pipeline ----
    float4 pv0, pv1, pv2, pv3, pxv;
    int pvalid, ploc;
    {
        int local = sub;                       // it = 0; sub < 8 <= NPB
        ploc   = local;
        pvalid = (blockStart + local < NN);
        int i = blockStart + local; if (i >= NN) i = NN - 1;
        int4 s = s_srcn[local];
        pv0 = (s.x < 0) ? bp : __ldg(&x4[(size_t)s.x * 32 + dg]);
        pv1 = (s.y < 0) ? bp : __ldg(&x4[(size_t)s.y * 32 + dg]);
        pv2 = (s.z < 0) ? bp : __ldg(&x4[(size_t)s.z * 32 + dg]);
        pv3 = (s.w < 0) ? bp : __ldg(&x4[(size_t)s.w * 32 + dg]);
        pxv = __ldg(&x4[(size_t)i * 32 + dg]);
    }

#pragma unroll
    for (int it = 0; it < NIT; it++) {
        float4 nv0, nv1, nv2, nv3, nxv;
        int nvalid = 0, nloc = 0;
        if (it + 1 < NIT) {                    // compile-time after unroll
            int local = (it + 1) * 8 + sub;
            nloc   = local;
            nvalid = (local < NPB) && (blockStart + local < NN);
            int li = (local < NPB) ? local : NPB - 1;
            int i = blockStart + li; if (i >= NN) i = NN - 1;
            int4 s = s_srcn[li];
            nv0 = (s.x < 0) ? bp : __ldg(&x4[(size_t)s.x * 32 + dg]);
            nv1 = (s.y < 0) ? bp : __ldg(&x4[(size_t)s.y * 32 + dg]);
            nv2 = (s.z < 0) ? bp : __ldg(&x4[(size_t)s.z * 32 + dg]);
            nv3 = (s.w < 0) ? bp : __ldg(&x4[(size_t)s.w * 32 + dg]);
            nxv = __ldg(&x4[(size_t)i * 32 + dg]);
        }

        if (pvalid) {
            float4 v0 = pv0, v1 = pv1, v2 = pv2, v3 = pv3;
            float t;
#define CSWAP(A,B) \
            t = fminf(A.x,B.x); B.x = fmaxf(A.x,B.x); A.x = t; \
            t = fminf(A.y,B.y); B.y = fmaxf(A.y,B.y); A.y = t; \
            t = fminf(A.z,B.z); B.z = fmaxf(A.z,B.z); A.z = t; \
            t = fminf(A.w,B.w); B.w = fmaxf(A.w,B.w); A.w = t;
            CSWAP(v0, v1)
            CSWAP(v2, v3)
            CSWAP(v0, v2)
            CSWAP(v1, v3)
            CSWAP(v1, v2)
#undef CSWAP
            float4 hv;
            hv.x = av * pxv.x + v0.x * c0 + v1.x * c1 + v2.x * c2 + v3.x * c3 + cbv;
            hv.y = av * pxv.y + v0.y * c0 + v1.y * c1 + v2.y * c2 + v3.y * c3 + cbv;
            hv.z = av * pxv.z + v0.z * c0 + v1.z * c1 + v2.z * c2 + v3.z * c3 + cbv;
            hv.w = av * pxv.w + v0.w * c0 + v1.w * c1 + v2.w * c2 + v3.w * c3 + cbv;
            sh[ploc * 32 + dg] = hv;
            lsum.x += hv.x; lsum.y += hv.y; lsum.z += hv.z; lsum.w += hv.w;
            lsq.x += hv.x * hv.x; lsq.y += hv.y * hv.y;
            lsq.z += hv.z * hv.z; lsq.w += hv.w * hv.w;
        }

        pv0 = nv0; pv1 = nv1; pv2 = nv2; pv3 = nv3; pxv = nxv;
        pvalid = nvalid; ploc = nloc;
    }

    // ---- block reduce + global partials ----
    ssum[threadIdx.x] = lsum;
    ssq[threadIdx.x]  = lsq;
    __syncthreads();
    if (threadIdx.x < 32) {
        float4 a = ssum[threadIdx.x];
        float4 q = ssq[threadIdx.x];
#pragma unroll
        for (int k = 1; k < 8; k++) {
            float4 a2 = ssum[threadIdx.x + 32 * k];
            float4 q2 = ssq[threadIdx.x + 32 * k];
            a.x += a2.x; a.y += a2.y; a.z += a2.z; a.w += a2.w;
            q.x += q2.x; q.y += q2.y; q.z += q2.z; q.w += q2.w;
        }
        int d0 = threadIdx.x * 4;
        atomicAdd(&g_sum[layer][d0 + 0], a.x);
        atomicAdd(&g_sum[layer][d0 + 1], a.y);
        atomicAdd(&g_sum[layer][d0 + 2], a.z);
        atomicAdd(&g_sum[layer][d0 + 3], a.w);
        atomicAdd(&g_sq[layer][d0 + 0], q.x);
        atomicAdd(&g_sq[layer][d0 + 1], q.y);
        atomicAdd(&g_sq[layer][d0 + 2], q.z);
        atomicAdd(&g_sq[layer][d0 + 3], q.w);
    }

    // ---- soft grid barrier (all blocks co-resident) ----
    __threadfence();
    if (threadIdx.x == 0) {
        atomicAdd(&g_done[layer], 1);
        volatile int* dp = &g_done[layer];
        while (*dp < NBLOCKS) { __nanosleep(100); }
    }
    __syncthreads();
    __threadfence();

    // ---- phase 2: stats + apply ----
    if (threadIdx.x < DD) {
        int d = threadIdx.x;
        float mu  = __ldcg(&g_sum[layer][d]) * (1.0f / NN);
        float var = __ldcg(&g_sq[layer][d]) * (1.0f / NN) - mu * mu;
        smu[d]    = mu;
        sscale[d] = rsqrtf(var + 1e-5f) * __ldg(&gamma[d]);
    }
    __syncthreads();

    int d0 = dg * 4;
    float m0 = smu[d0], m1 = smu[d0 + 1], m2 = smu[d0 + 2], m3 = smu[d0 + 3];
    float s0 = sscale[d0], s1 = sscale[d0 + 1], s2 = sscale[d0 + 2], s3 = sscale[d0 + 3];
    float e0 = __ldg(&beta[d0]), e1 = __ldg(&beta[d0 + 1]);
    float e2 = __ldg(&beta[d0 + 2]), e3 = __ldg(&beta[d0 + 3]);

#pragma unroll 4
    for (int it = 0; it < NIT; it++) {
        int local = it * 8 + sub;
        int i = blockStart + local;
        if (local < NPB && i < NN) {
            float4 hv = sh[local * 32 + dg];
            float4 xv = __ldg(&x4[(size_t)i * 32 + dg]);
            float4 o;
            o.x = xv.x + (hv.x - m0) * s0 + e0;
            o.y = xv.y + (hv.y - m1) * s1 + e1;
            o.z = xv.z + (hv.z - m2) * s2 + e2;
            o.w = xv.w + (hv.w - m3) * s3 + e3;
            out4[(size_t)i * 32 + dg] = o;
        }
    }
}

// ---------------- launch -----------------------------------------------------

extern "C" void kernel_launch(void* const* d_in, const int* in_sizes, int n_in,
                              void* d_out, int out_size)
{
    const float* x   = (const float*)d_in[0];
    const int*   ei  = (const int*)d_in[1];
    const int*   src = ei;        // edge_index[0]
    const int*   dst = ei + EE;   // edge_index[1]

    const float* W0     = (const float*)d_in[2];
    const float* b0     = (const float*)d_in[3];
    const float* cw0    = (const float*)d_in[4];
    const float* cb0    = (const float*)d_in[5];
    const float* a0     = (const float*)d_in[6];
    const float* g0     = (const float*)d_in[7];
    const float* be0    = (const float*)d_in[8];
    const float* blank0 = (const float*)d_in[9];
    const float* W1     = (const float*)d_in[10];
    const float* b1     = (const float*)d_in[11];
    const float* cw1    = (const float*)d_in[12];
    const float* cb1    = (const float*)d_in[13];
    const float* a1     = (const float*)d_in[14];
    const float* g1     = (const float*)d_in[15];
    const float* be1    = (const float*)d_in[16];
    const float* blank1 = (const float*)d_in[17];

    float* out = (float*)d_out;

    const int smem_bytes = NPB * 32 * sizeof(float4);   // 57,856 B

    static bool attr_set = false;
    if (!attr_set) {
        cudaFuncSetAttribute(fused_kernel,
                             cudaFuncAttributeMaxDynamicSharedMemorySize, smem_bytes);
        attr_set = true;
    }

    // scatter edges into buckets (+ extra block: blankp/stat-zero)
    scatter_kernel<<<SCAT_BLOCKS + 1, 256>>>((const int4*)dst,
                                             W0, b0, blank0, W1, b1, blank1);
    // per-bucket smem top-4 -> g_srcn (also resets bucket counters)
    bucket_kernel<<<NBUCKET, 256>>>(src);

    // layer 0: reads x, writes x1 into d_out
    fused_kernel<<<NBLOCKS, 256, smem_bytes>>>((const float4*)x, cw0, cb0, a0,
                                               g0, be0, (float4*)out, 0);
    // layer 1: reads d_out, writes final into d_out (safe: all gathers precede
    // any write because every write is after the grid barrier)
    fused_kernel<<<NBLOCKS, 256, smem_bytes>>>((const float4*)out, cw1, cb1, a1,
                                               g1, be1, (float4*)out, 1);
}

// round 17
// speedup vs baseline: 1.9184x; 1.9184x over previous
#include <cuda_runtime.h>
#include <cuda_bf16.h>
#include <math.h>

#define NN 50000
#define EE 800000
#define DD 128
#define MAXN 4
#define SLOT_INF 0xFFFFFFFFu
#define NBLOCKS 444            // 148 SMs x 3 resident blocks (co-resident by construction)
#define NPB 113                // ceil(50000/444) nodes per block
#define NIT 15                 // ceil(113/8) iterations per sub-lane
#define EDGE_BLOCKS ((EE / 4 + 255) / 256)

// ---------------- scratch (device globals; no allocation allowed) ----------
__device__ unsigned g_slots[NN * MAXN];    // 4 smallest in-edge ids per node
__device__ float    g_blankp[2][DD];
__device__ float    g_sum[2][DD];
__device__ float    g_sq[2][DD];
__device__ int      g_done[2];

// ---------------- kernels ---------------------------------------------------

// Edge pass (cascaded atomicMin with L1 stale-high prune) + one extra block
// computing blank_p (COALESCED warp-per-row matvec) and zeroing stats.
__global__ void edge_pass_kernel(const int4* __restrict__ dst4,
                                 const float* __restrict__ W0, const float* __restrict__ b0,
                                 const float* __restrict__ blank0,
                                 const float* __restrict__ W1, const float* __restrict__ b1,
                                 const float* __restrict__ blank1)
{
    if ((int)blockIdx.x < EDGE_BLOCKS) {
        int t = blockIdx.x * blockDim.x + threadIdx.x;
        if (t >= EE / 4) return;
        int4 d = __ldg(&dst4[t]);
        int e0 = t * 4;
#pragma unroll
        for (int j = 0; j < 4; j++) {
            int node = (j == 0) ? d.x : (j == 1) ? d.y : (j == 2) ? d.z : d.w;
            unsigned v = (unsigned)(e0 + j);
            unsigned* sl = &g_slots[node * MAXN];
            if (v >= sl[MAXN - 1]) continue;   // plain (L1-cacheable) stale-high read
#pragma unroll
            for (int k = 0; k < MAXN; k++) {
                unsigned old = atomicMin(&sl[k], v);
                if (old == SLOT_INF) break;   // inserted into empty slot
                v = max(v, old);              // displaced (larger) value cascades
            }
        }
    } else {
        // blankp for both layers (coalesced: warp-per-row) + zero stats.
        int t = threadIdx.x;           // 0..255 = 8 warps
        int w = t >> 5, lane = t & 31;
        int layer = w >> 2;            // warps 0-3 -> layer 0, warps 4-7 -> layer 1
        const float* W  = layer ? W1 : W0;
        const float* b  = layer ? b1 : b0;
        const float* bl = layer ? blank1 : blank0;
        float bl0 = __ldg(&bl[lane]);
        float bl1 = __ldg(&bl[lane + 32]);
        float bl2 = __ldg(&bl[lane + 64]);
        float bl3 = __ldg(&bl[lane + 96]);
        int rbase = (w & 3) * 32;      // each warp owns 32 rows
#pragma unroll 4
        for (int r = rbase; r < rbase + 32; r++) {
            const float* row = W + r * DD;
            float s = __ldg(&row[lane])      * bl0
                    + __ldg(&row[lane + 32]) * bl1
                    + __ldg(&row[lane + 64]) * bl2
                    + __ldg(&row[lane + 96]) * bl3;
#pragma unroll
            for (int off = 16; off; off >>= 1)
                s += __shfl_xor_sync(0xffffffffu, s, off);
            if (lane == 0) g_blankp[layer][r] = s + __ldg(&b[r]);
        }
        int layer2 = t >> 7, d = t & 127;
        g_sum[layer2][d] = 0.0f;
        g_sq[layer2][d]  = 0.0f;
        if (t == 0) { g_done[0] = 0; g_done[1] = 0; }
    }
}

// Fused persistent conv + batchnorm-apply, software-pipelined phase 1.
// Phase 0 converts this block's slot records (edge ids) into source-node ids
// directly in smem — no global srcn array, no prep kernel.
__global__ __launch_bounds__(256, 3) void fused_kernel(
    const float4* __restrict__ x4, const int* __restrict__ src,
    const float* __restrict__ cw, const float* __restrict__ cb,
    const float* __restrict__ a_p,
    const float* __restrict__ gamma, const float* __restrict__ beta,
    float4* __restrict__ out4, int layer)
{
    extern __shared__ float4 sh[];          // [NPB][32] h rows
    __shared__ int4   s_srcn[NPB];
    __shared__ float4 ssum[256];
    __shared__ float4 ssq[256];
    __shared__ float  smu[DD];
    __shared__ float  sscale[DD];

    int dg  = threadIdx.x & 31;    // dim group: dims 4*dg .. 4*dg+3
    int sub = threadIdx.x >> 5;    // 0..7 node sub-lanes
    float c0 = __ldg(cw + 0), c1 = __ldg(cw + 1), c2 = __ldg(cw + 2), c3 = __ldg(cw + 3);
    float cbv = __ldg(cb);
    float av  = __ldg(a_p);
    float4 bp = *reinterpret_cast<const float4*>(&g_blankp[layer][dg * 4]);

    int blockStart = blockIdx.x * NPB;

    // ---- phase 0: slots -> srcn window, straight into smem ----
    for (int k = threadIdx.x; k < NPB; k += 256) {
        int i = blockStart + k;
        int4 r = make_int4(-1, -1, -1, -1);
        if (i < NN) {
            uint4 s = *reinterpret_cast<const uint4*>(&g_slots[i * 4]);
            r.x = (s.x == SLOT_INF) ? -1 : __ldg(&src[s.x]);
            r.y = (s.y == SLOT_INF) ? -1 : __ldg(&src[s.y]);
            r.z = (s.z == SLOT_INF) ? -1 : __ldg(&src[s.z]);
            r.w = (s.w == SLOT_INF) ? -1 : __ldg(&src[s.w]);
        }
        s_srcn[k] = r;
    }
    __syncthreads();

    float4 lsum = make_float4(0.f, 0.f, 0.f, 0.f);
    float4 lsq  = make_float4(0.f, 0.f, 0.f, 0.f);

    // ---- phase 1: conv into smem, 2-stage software pipeline ----
    float4 pv0, pv1, pv2, pv3, pxv;
    int pvalid, ploc;
    {
        int local = sub;                       // it = 0; sub < 8 <= NPB
        ploc   = local;
        pvalid = (blockStart + local < NN);
        int i = blockStart + local; if (i >= NN) i = NN - 1;
        int4 s = s_srcn[local];
        pv0 = (s.x < 0) ? bp : __ldg(&x4[(size_t)s.x * 32 + dg]);
        pv1 = (s.y < 0) ? bp : __ldg(&x4[(size_t)s.y * 32 + dg]);
        pv2 = (s.z < 0) ? bp : __ldg(&x4[(size_t)s.z * 32 + dg]);
        pv3 = (s.w < 0) ? bp : __ldg(&x4[(size_t)s.w * 32 + dg]);
        pxv = __ldg(&x4[(size_t)i * 32 + dg]);
    }

#pragma unroll
    for (int it = 0; it < NIT; it++) {
        float4 nv0, nv1, nv2, nv3, nxv;
        int nvalid = 0, nloc = 0;
        if (it + 1 < NIT) {                    // compile-time after unroll
            int local = (it + 1) * 8 + sub;
            nloc   = local;
            nvalid = (local < NPB) && (blockStart + local < NN);
            int li = (local < NPB) ? local : NPB - 1;
            int i = blockStart + li; if (i >= NN) i = NN - 1;
            int4 s = s_srcn[li];
            nv0 = (s.x < 0) ? bp : __ldg(&x4[(size_t)s.x * 32 + dg]);
            nv1 = (s.y < 0) ? bp : __ldg(&x4[(size_t)s.y * 32 + dg]);
            nv2 = (s.z < 0) ? bp : __ldg(&x4[(size_t)s.z * 32 + dg]);
            nv3 = (s.w < 0) ? bp : __ldg(&x4[(size_t)s.w * 32 + dg]);
            nxv = __ldg(&x4[(size_t)i * 32 + dg]);
        }

        if (pvalid) {
            float4 v0 = pv0, v1 = pv1, v2 = pv2, v3 = pv3;
            float t;
#define CSWAP(A,B) \
            t = fminf(A.x,B.x); B.x = fmaxf(A.x,B.x); A.x = t; \
            t = fminf(A.y,B.y); B.y = fmaxf(A.y,B.y); A.y = t; \
            t = fminf(A.z,B.z); B.z = fmaxf(A.z,B.z); A.z = t; \
            t = fminf(A.w,B.w); B.w = fmaxf(A.w,B.w); A.w = t;
            CSWAP(v0, v1)
            CSWAP(v2, v3)
            CSWAP(v0, v2)
            CSWAP(v1, v3)
            CSWAP(v1, v2)
#undef CSWAP
            float4 hv;
            hv.x = av * pxv.x + v0.x * c0 + v1.x * c1 + v2.x * c2 + v3.x * c3 + cbv;
            hv.y = av * pxv.y + v0.y * c0 + v1.y * c1 + v2.y * c2 + v3.y * c3 + cbv;
            hv.z = av * pxv.z + v0.z * c0 + v1.z * c1 + v2.z * c2 + v3.z * c3 + cbv;
            hv.w = av * pxv.w + v0.w * c0 + v1.w * c1 + v2.w * c2 + v3.w * c3 + cbv;
            sh[ploc * 32 + dg] = hv;
            lsum.x += hv.x; lsum.y += hv.y; lsum.z += hv.z; lsum.w += hv.w;
            lsq.x += hv.x * hv.x; lsq.y += hv.y * hv.y;
            lsq.z += hv.z * hv.z; lsq.w += hv.w * hv.w;
        }

        pv0 = nv0; pv1 = nv1; pv2 = nv2; pv3 = nv3; pxv = nxv;
        pvalid = nvalid; ploc = nloc;
    }

    // ---- block reduce + global partials ----
    ssum[threadIdx.x] = lsum;
    ssq[threadIdx.x]  = lsq;
    __syncthreads();
    if (threadIdx.x < 32) {
        float4 a = ssum[threadIdx.x];
        float4 q = ssq[threadIdx.x];
#pragma unroll
        for (int k = 1; k < 8; k++) {
            float4 a2 = ssum[threadIdx.x + 32 * k];
            float4 q2 = ssq[threadIdx.x + 32 * k];
            a.x += a2.x; a.y += a2.y; a.z += a2.z; a.w += a2.w;
            q.x += q2.x; q.y += q2.y; q.z += q2.z; q.w += q2.w;
        }
        int d0 = threadIdx.x * 4;
        atomicAdd(&g_sum[layer][d0 + 0], a.x);
        atomicAdd(&g_sum[layer][d0 + 1], a.y);
        atomicAdd(&g_sum[layer][d0 + 2], a.z);
        atomicAdd(&g_sum[layer][d0 + 3], a.w);
        atomicAdd(&g_sq[layer][d0 + 0], q.x);
        atomicAdd(&g_sq[layer][d0 + 1], q.y);
        atomicAdd(&g_sq[layer][d0 + 2], q.z);
        atomicAdd(&g_sq[layer][d0 + 3], q.w);
    }

    // ---- soft grid barrier (all blocks co-resident) ----
    __threadfence();
    if (threadIdx.x == 0) {
        atomicAdd(&g_done[layer], 1);
        volatile int* dp = &g_done[layer];
        while (*dp < NBLOCKS) { __nanosleep(100); }
    }
    __syncthreads();
    __threadfence();

    // ---- phase 2: stats + apply ----
    if (threadIdx.x < DD) {
        int d = threadIdx.x;
        float mu  = __ldcg(&g_sum[layer][d]) * (1.0f / NN);
        float var = __ldcg(&g_sq[layer][d]) * (1.0f / NN) - mu * mu;
        smu[d]    = mu;
        sscale[d] = rsqrtf(var + 1e-5f) * __ldg(&gamma[d]);
    }
    __syncthreads();

    int d0 = dg * 4;
    float m0 = smu[d0], m1 = smu[d0 + 1], m2 = smu[d0 + 2], m3 = smu[d0 + 3];
    float s0 = sscale[d0], s1 = sscale[d0 + 1], s2 = sscale[d0 + 2], s3 = sscale[d0 + 3];
    float e0 = __ldg(&beta[d0]), e1 = __ldg(&beta[d0 + 1]);
    float e2 = __ldg(&beta[d0 + 2]), e3 = __ldg(&beta[d0 + 3]);

#pragma unroll 4
    for (int it = 0; it < NIT; it++) {
        int local = it * 8 + sub;
        int i = blockStart + local;
        if (local < NPB && i < NN) {
            float4 hv = sh[local * 32 + dg];
            float4 xv = __ldg(&x4[(size_t)i * 32 + dg]);
            float4 o;
            o.x = xv.x + (hv.x - m0) * s0 + e0;
            o.y = xv.y + (hv.y - m1) * s1 + e1;
            o.z = xv.z + (hv.z - m2) * s2 + e2;
            o.w = xv.w + (hv.w - m3) * s3 + e3;
            out4[(size_t)i * 32 + dg] = o;
        }
    }
}

// ---------------- launch -----------------------------------------------------

extern "C" void kernel_launch(void* const* d_in, const int* in_sizes, int n_in,
                              void* d_out, int out_size)
{
    const float* x   = (const float*)d_in[0];
    const int*   ei  = (const int*)d_in[1];
    const int*   src = ei;        // edge_index[0]
    const int*   dst = ei + EE;   // edge_index[1]

    const float* W0     = (const float*)d_in[2];
    const float* b0     = (const float*)d_in[3];
    const float* cw0    = (const float*)d_in[4];
    const float* cb0    = (const float*)d_in[5];
    const float* a0     = (const float*)d_in[6];
    const float* g0     = (const float*)d_in[7];
    const float* be0    = (const float*)d_in[8];
    const float* blank0 = (const float*)d_in[9];
    const float* W1     = (const float*)d_in[10];
    const float* b1     = (const float*)d_in[11];
    const float* cw1    = (const float*)d_in[12];
    const float* cb1    = (const float*)d_in[13];
    const float* a1     = (const float*)d_in[14];
    const float* g1     = (const float*)d_in[15];
    const float* be1    = (const float*)d_in[16];
    const float* blank1 = (const float*)d_in[17];

    float* out = (float*)d_out;

    const int smem_bytes = NPB * 32 * sizeof(float4);   // 57,856 B

    static bool attr_set = false;
    if (!attr_set) {
        cudaFuncSetAttribute(fused_kernel,
                             cudaFuncAttributeMaxDynamicSharedMemorySize, smem_bytes);
        attr_set = true;
    }

    // slots init: 0xFF byte pattern == SLOT_INF (unsigned), via async memset
    void* slots_ptr = nullptr;
    cudaGetSymbolAddress(&slots_ptr, g_slots);
    cudaMemsetAsync(slots_ptr, 0xFF, sizeof(unsigned) * NN * MAXN);

    // edge pass + (extra block) coalesced blankp/stat-zero
    edge_pass_kernel<<<EDGE_BLOCKS + 1, 256>>>((const int4*)dst,
                                               W0, b0, blank0, W1, b1, blank1);

    // layer 0: reads x, writes x1 into d_out
    fused_kernel<<<NBLOCKS, 256, smem_bytes>>>((const float4*)x, src, cw0, cb0, a0,
                                               g0, be0, (float4*)out, 0);
    // layer 1: reads d_out, writes final into d_out (safe: all gathers precede
    // any write because every write is after the grid barrier)
    fused_kernel<<<NBLOCKS, 256, smem_bytes>>>((const float4*)out, src, cw1, cb1, a1,
                                               g1, be1, (float4*)out, 1);
}